// round 4
// baseline (speedup 1.0000x reference)
#include <cuda_runtime.h>
#include <math.h>

#define HID     1024
#define BATCH   32
#define NLAYERS 3
#define NOUT    2500
#define NG      50
#define MODES   32
#define GATES   (3*HID)
#define KC      64
#define NCHUNK  (HID/KC)     // 16
#define JB      8            // hidden units per block (1 per warp, 8 warps)
#define FC_NB   32           // fc outputs per block (4 per warp, 8 warps)

// Activation layout: k-pair interleaved. Feature k, batch b lives at
//   addr = (k>>1)*64 + 2*b + (k&1)
// so one 8-byte read at [(k>>1)*64 + 2*b] yields (v[k even], v[k odd]) for batch b.
__device__ float g_h[2][NLAYERS][HID * BATCH];
__device__ float g_x[HID * BATCH];
__device__ float g_ct[NG];
__device__ float g_st[NG];

// ---------------- packed fp32x2 fma ----------------
__device__ __forceinline__ void ffma2(unsigned long long& acc,
                                      unsigned long long w,
                                      unsigned long long xh) {
    asm volatile("fma.rn.f32x2 %0, %1, %2, %0;" : "+l"(acc) : "l"(w), "l"(xh));
}
__device__ __forceinline__ float hsum2(unsigned long long v) {
    float2 f = *reinterpret_cast<float2*>(&v);
    return f.x + f.y;
}
union F4U2 { float4 f4; ulonglong2 u2; };

// ---------------- cp.async helpers ----------------
__device__ __forceinline__ void cp16(void* dst, const void* src) {
    unsigned d = (unsigned)__cvta_generic_to_shared(dst);
    asm volatile("cp.async.cg.shared.global [%0], [%1], 16;\n" :: "r"(d), "l"(src));
}
__device__ __forceinline__ void cp_commit() { asm volatile("cp.async.commit_group;\n"); }
template<int N> __device__ __forceinline__ void cp_wait() {
    asm volatile("cp.async.wait_group %0;\n" :: "n"(N));
}

// ---------------- init ----------------
__global__ void init_kernel(const float* __restrict__ x) {
    int tid = blockIdx.x * blockDim.x + threadIdx.x;
    int stride = gridDim.x * blockDim.x;
    float* h = (float*)g_h;
    int total = 2 * NLAYERS * HID * BATCH;
    for (int i = tid; i < total; i += stride) h[i] = 0.0f;
    for (int i = tid; i < HID * BATCH; i += stride) {
        int j = i >> 5, b = i & 31;
        g_x[(j >> 1) * 64 + 2 * b + (j & 1)] = x[b * HID + j];
    }
    if (tid < NG) {
        float ang = 6.283185307179586f * (float)tid / (float)NG;
        g_ct[tid] = cosf(ang);
        g_st[tid] = sinf(ang);
    }
}

// ---------------- GRU layer ----------------
// 256 threads = 8 warps; warp w owns j = blockIdx.x*8 + w; lane = batch.
// grid = 128 (<=148 SMs, perfectly balanced).
__global__ __launch_bounds__(256) void gru_kernel(
    const float* __restrict__ xT,     // interleaved [k/2][b][2]
    const float* __restrict__ hT,     // interleaved
    float*       __restrict__ hnT,    // interleaved
    const float* __restrict__ Wih,    // [3*HID][HID]
    const float* __restrict__ Whh,    // [3*HID][HID]
    const float* __restrict__ bih,
    const float* __restrict__ bhh)
{
    __shared__ __align__(16) float  Ws[2][JB * 6][KC];       // 24 KB
    __shared__ __align__(16) float2 Xp[2][KC / 2][BATCH];    // 16 KB
    __shared__ __align__(16) float2 Hp[2][KC / 2][BATCH];    // 16 KB

    const int tid  = threadIdx.x;
    const int warp = tid >> 5;
    const int lane = tid & 31;
    const int j0   = blockIdx.x * JB;

    // chunk: weights 48 rows x 16 segs = 768 cp16; X,H: 32 rows x 16 segs each.
    // total 1792 = 7 * 256.
    auto load_chunk = [&](int c, int buf) {
        const int kb = c * KC;          // k offset
        const int rb = c * (KC / 2);    // pair-row offset in activations
        #pragma unroll
        for (int it = 0; it < 7; ++it) {
            int i = tid + it * 256;
            if (i < 768) {
                int jg = i >> 4, off = i & 15;
                int jl = jg / 6, g = jg % 6;
                const float* base = (g < 3)
                    ? Wih + ((size_t)g * HID + j0 + jl) * HID
                    : Whh + ((size_t)(g - 3) * HID + j0 + jl) * HID;
                cp16(&Ws[buf][jg][off * 4], base + kb + off * 4);
            } else if (i < 1280) {
                int r = i - 768; int row = r >> 4, off = r & 15;
                cp16((float*)&Xp[buf][row][0] + off * 4, xT + (size_t)(rb + row) * 64 + off * 4);
            } else {
                int r = i - 1280; int row = r >> 4, off = r & 15;
                cp16((float*)&Hp[buf][row][0] + off * 4, hT + (size_t)(rb + row) * 64 + off * 4);
            }
        }
        cp_commit();
    };

    unsigned long long a0 = 0, a1 = 0, a2 = 0, a3 = 0, a4 = 0, a5 = 0;

    load_chunk(0, 0);
    for (int c = 0; c < NCHUNK; ++c) {
        const int buf = c & 1;
        if (c + 1 < NCHUNK) { load_chunk(c + 1, buf ^ 1); cp_wait<1>(); }
        else                { cp_wait<0>(); }
        __syncthreads();

        #pragma unroll
        for (int k4 = 0; k4 < KC / 4; ++k4) {
            F4U2 w0, w1, w2, w3, w4, w5;
            w0.f4 = *(const float4*)&Ws[buf][warp * 6 + 0][k4 * 4];
            w1.f4 = *(const float4*)&Ws[buf][warp * 6 + 1][k4 * 4];
            w2.f4 = *(const float4*)&Ws[buf][warp * 6 + 2][k4 * 4];
            w3.f4 = *(const float4*)&Ws[buf][warp * 6 + 3][k4 * 4];
            w4.f4 = *(const float4*)&Ws[buf][warp * 6 + 4][k4 * 4];
            w5.f4 = *(const float4*)&Ws[buf][warp * 6 + 5][k4 * 4];
            unsigned long long xv0 = *(const unsigned long long*)&Xp[buf][2 * k4 + 0][lane];
            unsigned long long xv1 = *(const unsigned long long*)&Xp[buf][2 * k4 + 1][lane];
            unsigned long long hv0 = *(const unsigned long long*)&Hp[buf][2 * k4 + 0][lane];
            unsigned long long hv1 = *(const unsigned long long*)&Hp[buf][2 * k4 + 1][lane];
            ffma2(a0, w0.u2.x, xv0); ffma2(a0, w0.u2.y, xv1);
            ffma2(a1, w1.u2.x, xv0); ffma2(a1, w1.u2.y, xv1);
            ffma2(a2, w2.u2.x, xv0); ffma2(a2, w2.u2.y, xv1);
            ffma2(a3, w3.u2.x, hv0); ffma2(a3, w3.u2.y, hv1);
            ffma2(a4, w4.u2.x, hv0); ffma2(a4, w4.u2.y, hv1);
            ffma2(a5, w5.u2.x, hv0); ffma2(a5, w5.u2.y, hv1);
        }
        __syncthreads();
    }

    const int j = j0 + warp;
    float ir  = hsum2(a0) + bih[j];
    float iz  = hsum2(a1) + bih[HID + j];
    float inn = hsum2(a2) + bih[2 * HID + j];
    float hr  = hsum2(a3) + bhh[j];
    float hz  = hsum2(a4) + bhh[HID + j];
    float hn  = hsum2(a5) + bhh[2 * HID + j];
    float r = 1.0f / (1.0f + __expf(-(ir + hr)));
    float z = 1.0f / (1.0f + __expf(-(iz + hz)));
    float n = tanhf(inn + r * hn);
    const size_t addr = (size_t)(j >> 1) * 64 + 2 * lane + (j & 1);
    float hp = hT[addr];
    hnT[addr] = (1.0f - z) * n + z * hp;
}

// ---------------- FC ----------------
// 256 threads = 8 warps; warp owns 4 outputs; lane = batch. grid = 79.
__global__ __launch_bounds__(256) void fc_kernel(
    const float* __restrict__ hT,    // interleaved
    const float* __restrict__ fcw,   // [NOUT][HID]
    const float* __restrict__ fcb,
    float*       __restrict__ out)   // [BATCH][NOUT] slice
{
    __shared__ __align__(16) float  Ws[2][FC_NB][KC];        // 16 KB
    __shared__ __align__(16) float2 Hp[2][KC / 2][BATCH];    // 16 KB

    const int tid  = threadIdx.x;
    const int warp = tid >> 5;
    const int lane = tid & 31;
    const int n0   = blockIdx.x * FC_NB;

    // 512 (weights) + 512 (H) cp16 = 4 per thread
    auto load_chunk = [&](int c, int buf) {
        const int kb = c * KC;
        const int rb = c * (KC / 2);
        #pragma unroll
        for (int it = 0; it < 4; ++it) {
            int i = tid + it * 256;
            if (i < 512) {
                int row = i >> 4, off = i & 15;
                int n = n0 + row; if (n > NOUT - 1) n = NOUT - 1;
                cp16(&Ws[buf][row][off * 4], fcw + (size_t)n * HID + kb + off * 4);
            } else {
                int r = i - 512; int row = r >> 4, off = r & 15;
                cp16((float*)&Hp[buf][row][0] + off * 4, hT + (size_t)(rb + row) * 64 + off * 4);
            }
        }
        cp_commit();
    };

    unsigned long long a0 = 0, a1 = 0, a2 = 0, a3 = 0;

    load_chunk(0, 0);
    for (int c = 0; c < NCHUNK; ++c) {
        const int buf = c & 1;
        if (c + 1 < NCHUNK) { load_chunk(c + 1, buf ^ 1); cp_wait<1>(); }
        else                { cp_wait<0>(); }
        __syncthreads();

        #pragma unroll
        for (int k4 = 0; k4 < KC / 4; ++k4) {
            F4U2 w0, w1, w2, w3;
            w0.f4 = *(const float4*)&Ws[buf][warp * 4 + 0][k4 * 4];
            w1.f4 = *(const float4*)&Ws[buf][warp * 4 + 1][k4 * 4];
            w2.f4 = *(const float4*)&Ws[buf][warp * 4 + 2][k4 * 4];
            w3.f4 = *(const float4*)&Ws[buf][warp * 4 + 3][k4 * 4];
            unsigned long long hv0 = *(const unsigned long long*)&Hp[buf][2 * k4 + 0][lane];
            unsigned long long hv1 = *(const unsigned long long*)&Hp[buf][2 * k4 + 1][lane];
            ffma2(a0, w0.u2.x, hv0); ffma2(a0, w0.u2.y, hv1);
            ffma2(a1, w1.u2.x, hv0); ffma2(a1, w1.u2.y, hv1);
            ffma2(a2, w2.u2.x, hv0); ffma2(a2, w2.u2.y, hv1);
            ffma2(a3, w3.u2.x, hv0); ffma2(a3, w3.u2.y, hv1);
        }
        __syncthreads();
    }

    const int n = n0 + warp * 4;
    if (n + 0 < NOUT) out[(size_t)lane * NOUT + n + 0] = hsum2(a0) + fcb[n + 0];
    if (n + 1 < NOUT) out[(size_t)lane * NOUT + n + 1] = hsum2(a1) + fcb[n + 1];
    if (n + 2 < NOUT) out[(size_t)lane * NOUT + n + 2] = hsum2(a2) + fcb[n + 2];
    if (n + 3 < NOUT) out[(size_t)lane * NOUT + n + 3] = hsum2(a3) + fcb[n + 3];
}

// ---------------- spectral crop ----------------
__global__ __launch_bounds__(256) void spectral_kernel(
    const float* __restrict__ out)   // [BATCH][NOUT] slice just written
{
    __shared__ float sq[NG * NG];
    __shared__ float Pc[NG][MODES];
    __shared__ float Ps[NG][MODES];
    __shared__ float ct[NG], st[NG];

    const int b = blockIdx.x;
    const int tid = threadIdx.x;
    const float* o = out + (size_t)b * NOUT;

    for (int i = tid; i < NOUT; i += 256) sq[i] = o[i];
    if (tid < NG) { ct[tid] = g_ct[tid]; st[tid] = g_st[tid]; }
    __syncthreads();

    for (int i = tid; i < NG * MODES; i += 256) {
        int n1 = i / MODES, m2 = i % MODES;
        int k2 = (m2 + 34) % NG;
        float sc = 0.f, ss = 0.f;
        int idx = 0;
        #pragma unroll 1
        for (int n2 = 0; n2 < NG; ++n2) {
            float v = sq[n1 * NG + n2];
            sc += v * ct[idx];
            ss += v * st[idx];
            idx += k2; if (idx >= NG) idx -= NG;
        }
        Pc[n1][m2] = sc;
        Ps[n1][m2] = ss;
    }
    __syncthreads();

    for (int i = tid; i < MODES * MODES; i += 256) {
        int m1 = i / MODES, m2 = i % MODES;
        int k1 = (m1 + 34) % NG;
        float acc = 0.f;
        int idx = 0;
        #pragma unroll 1
        for (int n1 = 0; n1 < NG; ++n1) {
            acc += ct[idx] * Pc[n1][m2] - st[idx] * Ps[n1][m2];
            idx += k1; if (idx >= NG) idx -= NG;
        }
        g_x[(i >> 1) * 64 + 2 * b + (i & 1)] = acc;   // interleaved store
    }
}

// ---------------- driver ----------------
extern "C" void kernel_launch(void* const* d_in, const int* in_sizes, int n_in,
                              void* d_out, int out_size) {
    const float* x   = (const float*)d_in[0];
    const float* Wih = (const float*)d_in[1];
    const float* Whh = (const float*)d_in[2];
    const float* bih = (const float*)d_in[3];
    const float* bhh = (const float*)d_in[4];
    const float* fcw = (const float*)d_in[5];
    const float* fcb = (const float*)d_in[6];
    float* out = (float*)d_out;

    const int T = out_size / (BATCH * NOUT);

    float* hbase; cudaGetSymbolAddress((void**)&hbase, g_h);
    float* xbase; cudaGetSymbolAddress((void**)&xbase, g_x);

    init_kernel<<<96, 256>>>(x);

    for (int t = 0; t < T; ++t) {
        const int p = t & 1, c = p ^ 1;
        const float* inp = xbase;
        for (int l = 0; l < NLAYERS; ++l) {
            const float* hp = hbase + ((size_t)p * NLAYERS + l) * HID * BATCH;
            float*       hc = hbase + ((size_t)c * NLAYERS + l) * HID * BATCH;
            gru_kernel<<<HID / JB, 256>>>(inp, hp, hc,
                                          Wih + (size_t)l * GATES * HID,
                                          Whh + (size_t)l * GATES * HID,
                                          bih + l * GATES,
                                          bhh + l * GATES);
            inp = hc;
        }
        float* oslice = out + (size_t)t * BATCH * NOUT;
        fc_kernel<<<(NOUT + FC_NB - 1) / FC_NB, 256>>>(
            hbase + ((size_t)c * NLAYERS + (NLAYERS - 1)) * HID * BATCH, fcw, fcb, oslice);
        spectral_kernel<<<BATCH, 256>>>(oslice);
    }
}